// round 6
// baseline (speedup 1.0000x reference)
#include <cuda_runtime.h>
#include <cuda_bf16.h>

// LSTM_8589935226: B=4194304, T=4, I=1, H=2, C=1.
// Two batch elements per thread; fully unrolled 4-step LSTM in registers.
// Streaming problem: 64MB in (x, one float4 per element) + 16MB out.
// Predicted DRAM-bound, ~13-17us. No tensor-core work exists at these shapes.

__device__ __forceinline__ float fsig(float x) {
    // sigmoid(x) = 1 / (1 + e^-x)
    return __fdividef(1.0f, 1.0f + __expf(-x));
}
__device__ __forceinline__ float ftanhf(float x) {
    // tanh(x) = 2/(1+e^-2x) - 1
    return __fdividef(2.0f, 1.0f + __expf(-2.0f * x)) - 1.0f;
}

__global__ __launch_bounds__(256) void lstm_fused_kernel(
    const float4* __restrict__ x,      // [B, T=4, I=1] -> one float4 per b
    const float*  __restrict__ W_ih,   // [8,1]
    const float*  __restrict__ W_hh,   // [8,2] row-major
    const float*  __restrict__ b_ih,   // [8]
    const float*  __restrict__ b_hh,   // [8]
    const float*  __restrict__ W_fc,   // [1,2]
    const float*  __restrict__ b_fc,   // [1]
    float2*       __restrict__ out,    // [B] viewed as [B/2] float2
    int nPairs)                        // B/2
{
    const int p = blockIdx.x * blockDim.x + threadIdx.x;
    if (p >= nPairs) return;

    // Front-batched independent loads: 2x LDG.128 (MLP_p1 = 2).
    const float4 xa = x[2 * p + 0];
    const float4 xb = x[2 * p + 1];
    float xta[4] = {xa.x, xa.y, xa.z, xa.w};
    float xtb[4] = {xb.x, xb.y, xb.z, xb.w};

    // Broadcast weight loads — uniform, L1-resident after first warp.
    float wih[8], bs[8], wh0[8], wh1[8];
#pragma unroll
    for (int k = 0; k < 8; ++k) {
        wih[k] = __ldg(W_ih + k);
        bs[k]  = __ldg(b_ih + k) + __ldg(b_hh + k);
        wh0[k] = __ldg(W_hh + 2 * k + 0);
        wh1[k] = __ldg(W_hh + 2 * k + 1);
    }
    const float wfc0 = __ldg(W_fc + 0);
    const float wfc1 = __ldg(W_fc + 1);
    const float bfc  = __ldg(b_fc);

    // PyTorch gate packing: a[0..1]=i, a[2..3]=f, a[4..5]=g, a[6..7]=o
    float ha0 = 0.f, ha1 = 0.f, ca0 = 0.f, ca1 = 0.f;
    float hb0 = 0.f, hb1 = 0.f, cb0 = 0.f, cb1 = 0.f;
#pragma unroll
    for (int t = 0; t < 4; ++t) {
        float A[8], Bt[8];
#pragma unroll
        for (int k = 0; k < 8; ++k) {
            A[k]  = fmaf(xta[t], wih[k], fmaf(ha0, wh0[k], fmaf(ha1, wh1[k], bs[k])));
            Bt[k] = fmaf(xtb[t], wih[k], fmaf(hb0, wh0[k], fmaf(hb1, wh1[k], bs[k])));
        }
        // element a
        {
            const float i0 = fsig(A[0]),  i1 = fsig(A[1]);
            const float f0 = fsig(A[2]),  f1 = fsig(A[3]);
            const float g0 = ftanhf(A[4]), g1 = ftanhf(A[5]);
            const float o0 = fsig(A[6]),  o1 = fsig(A[7]);
            ca0 = fmaf(f0, ca0, i0 * g0);
            ca1 = fmaf(f1, ca1, i1 * g1);
            ha0 = o0 * ftanhf(ca0);
            ha1 = o1 * ftanhf(ca1);
        }
        // element b (independent chain — ILP)
        {
            const float i0 = fsig(Bt[0]),  i1 = fsig(Bt[1]);
            const float f0 = fsig(Bt[2]),  f1 = fsig(Bt[3]);
            const float g0 = ftanhf(Bt[4]), g1 = ftanhf(Bt[5]);
            const float o0 = fsig(Bt[6]),  o1 = fsig(Bt[7]);
            cb0 = fmaf(f0, cb0, i0 * g0);
            cb1 = fmaf(f1, cb1, i1 * g1);
            hb0 = o0 * ftanhf(cb0);
            hb1 = o1 * ftanhf(cb1);
        }
    }

    float2 r;
    r.x = fmaf(ha0, wfc0, fmaf(ha1, wfc1, bfc));
    r.y = fmaf(hb0, wfc0, fmaf(hb1, wfc1, bfc));
    out[p] = r;  // STG.64, coalesced
}

extern "C" void kernel_launch(void* const* d_in, const int* in_sizes, int n_in,
                              void* d_out, int out_size) {
    // metadata order: x, W_ih, W_hh, b_ih, b_hh, W_fc, b_fc
    const float4* x    = (const float4*)d_in[0];
    const float*  W_ih = (const float*)d_in[1];
    const float*  W_hh = (const float*)d_in[2];
    const float*  b_ih = (const float*)d_in[3];
    const float*  b_hh = (const float*)d_in[4];
    const float*  W_fc = (const float*)d_in[5];
    const float*  b_fc = (const float*)d_in[6];
    float2* out = (float2*)d_out;

    const int Bn     = in_sizes[0] / 4;   // x has B*T*I = B*4 floats
    const int nPairs = Bn / 2;            // B is even (4194304)
    const int threads = 256;
    const int blocks  = (nPairs + threads - 1) / threads;  // 8192
    lstm_fused_kernel<<<blocks, threads>>>(x, W_ih, W_hh, b_ih, b_hh, W_fc, b_fc,
                                           out, nPairs);
}

// round 17
// speedup vs baseline: 1.6545x; 1.6545x over previous
#include <cuda_runtime.h>
#include <cuda_bf16.h>

// LSTM_8589935226: B=4194304, T=4, I=1, H=2, C=1.
// R6 post-mortem: kernel is MUFU-bound (EX2+RCP per activation = 20 MUFU/elem/step
// -> 71us model matched 68us measured; DRAM only 13%).
// R7: tanh.approx.f32 (1 MUFU per activation, 10/elem/step) + packed f32x2
// arithmetic across the 2 batch elements per thread (halves fma-pipe instrs).
// Predicted ~37-42us (MUFU-bound at ~35us floor).

typedef unsigned long long u64;

__device__ __forceinline__ u64 pack2(float lo, float hi) {
    u64 r; asm("mov.b64 %0, {%1, %2};" : "=l"(r) : "f"(lo), "f"(hi)); return r;
}
__device__ __forceinline__ void unpack2(u64 v, float& lo, float& hi) {
    asm("mov.b64 {%0, %1}, %2;" : "=f"(lo), "=f"(hi) : "l"(v));
}
__device__ __forceinline__ u64 fma2_(u64 a, u64 b, u64 c) {
    u64 d; asm("fma.rn.f32x2 %0, %1, %2, %3;" : "=l"(d) : "l"(a), "l"(b), "l"(c)); return d;
}
__device__ __forceinline__ u64 mul2_(u64 a, u64 b) {
    u64 d; asm("mul.rn.f32x2 %0, %1, %2;" : "=l"(d) : "l"(a), "l"(b)); return d;
}
__device__ __forceinline__ float tanh_ap(float x) {
    float y; asm("tanh.approx.f32 %0, %1;" : "=f"(y) : "f"(x)); return y;
}
__device__ __forceinline__ u64 tanh2_(u64 v) {
    float lo, hi; unpack2(v, lo, hi);
    return pack2(tanh_ap(lo), tanh_ap(hi));
}
// sigmoid(x) = 0.5*tanh(0.5*x) + 0.5, elementwise on a packed pair
__device__ __forceinline__ u64 sig2_(u64 a, u64 c05) {
    return fma2_(tanh2_(mul2_(a, c05)), c05, c05);
}

__global__ __launch_bounds__(256) void lstm_fused_kernel(
    const float4* __restrict__ x,      // [B, T=4, I=1] -> one float4 per b
    const float*  __restrict__ W_ih,   // [8,1]
    const float*  __restrict__ W_hh,   // [8,2] row-major
    const float*  __restrict__ b_ih,   // [8]
    const float*  __restrict__ b_hh,   // [8]
    const float*  __restrict__ W_fc,   // [1,2]
    const float*  __restrict__ b_fc,   // [1]
    float2*       __restrict__ out,    // [B] viewed as [B/2] float2
    int nPairs)                        // B/2
{
    const int p = blockIdx.x * blockDim.x + threadIdx.x;
    if (p >= nPairs) return;

    // Front-batched independent loads: 2x LDG.128 (MLP_p1 = 2).
    const float4 xa = x[2 * p + 0];
    const float4 xb = x[2 * p + 1];
    // Packed per-timestep inputs: lane lo = element a, lane hi = element b.
    u64 px[4];
    px[0] = pack2(xa.x, xb.x);
    px[1] = pack2(xa.y, xb.y);
    px[2] = pack2(xa.z, xb.z);
    px[3] = pack2(xa.w, xb.w);

    // Broadcast weights, duplicated into both lanes of packed regs.
    u64 wih2[8], bs2[8], wh02[8], wh12[8];
#pragma unroll
    for (int k = 0; k < 8; ++k) {
        const float w  = __ldg(W_ih + k);
        const float bb = __ldg(b_ih + k) + __ldg(b_hh + k);
        const float w0 = __ldg(W_hh + 2 * k + 0);
        const float w1 = __ldg(W_hh + 2 * k + 1);
        wih2[k] = pack2(w, w);
        bs2[k]  = pack2(bb, bb);
        wh02[k] = pack2(w0, w0);
        wh12[k] = pack2(w1, w1);
    }
    const float wfc0 = __ldg(W_fc + 0);
    const float wfc1 = __ldg(W_fc + 1);
    const float bfc  = __ldg(b_fc);

    const u64 c05 = pack2(0.5f, 0.5f);

    // PyTorch gate packing: a[0..1]=i, a[2..3]=f, a[4..5]=g, a[6..7]=o
    u64 h0 = 0ull, h1 = 0ull, c0 = 0ull, c1 = 0ull;  // 0ull == (0.0f, 0.0f)
#pragma unroll
    for (int t = 0; t < 4; ++t) {
        u64 a[8];
#pragma unroll
        for (int k = 0; k < 8; ++k)
            a[k] = fma2_(px[t], wih2[k],
                   fma2_(h0, wh02[k],
                   fma2_(h1, wh12[k], bs2[k])));

        const u64 i0 = sig2_(a[0], c05);
        const u64 i1 = sig2_(a[1], c05);
        const u64 f0 = sig2_(a[2], c05);
        const u64 f1 = sig2_(a[3], c05);
        const u64 g0 = tanh2_(a[4]);
        const u64 g1 = tanh2_(a[5]);
        const u64 o0 = sig2_(a[6], c05);
        const u64 o1 = sig2_(a[7], c05);

        c0 = fma2_(f0, c0, mul2_(i0, g0));
        c1 = fma2_(f1, c1, mul2_(i1, g1));
        h0 = mul2_(o0, tanh2_(c0));
        h1 = mul2_(o1, tanh2_(c1));
    }

    float h0a, h0b, h1a, h1b;
    unpack2(h0, h0a, h0b);
    unpack2(h1, h1a, h1b);

    float2 r;
    r.x = fmaf(h0a, wfc0, fmaf(h1a, wfc1, bfc));
    r.y = fmaf(h0b, wfc0, fmaf(h1b, wfc1, bfc));
    out[p] = r;  // STG.64, coalesced
}

extern "C" void kernel_launch(void* const* d_in, const int* in_sizes, int n_in,
                              void* d_out, int out_size) {
    // metadata order: x, W_ih, W_hh, b_ih, b_hh, W_fc, b_fc
    const float4* x    = (const float4*)d_in[0];
    const float*  W_ih = (const float*)d_in[1];
    const float*  W_hh = (const float*)d_in[2];
    const float*  b_ih = (const float*)d_in[3];
    const float*  b_hh = (const float*)d_in[4];
    const float*  W_fc = (const float*)d_in[5];
    const float*  b_fc = (const float*)d_in[6];
    float2* out = (float2*)d_out;

    const int Bn      = in_sizes[0] / 4;   // x has B*T*I = B*4 floats
    const int nPairs  = Bn / 2;            // B is even (4194304)
    const int threads = 256;
    const int blocks  = (nPairs + threads - 1) / threads;
    lstm_fused_kernel<<<blocks, threads>>>(x, W_ih, W_hh, b_ih, b_hh, W_fc, b_fc,
                                           out, nPairs);
}